// round 13
// baseline (speedup 1.0000x reference)
#include <cuda_runtime.h>
#include <cuda_bf16.h>

#define BB 8
#define NN 16384
#define DD 512
#define MV 8
#define SS 128                      // N-splits in pass 1
#define RPS (NN / SS)               // rows per split = 128
#define NBLK 128                    // blocks per batch in pass 3
#define SCALE_F 0.1f
#define EPS_F 1e-5f

__device__ float g_partial[BB][SS][DD];        // 2 MB  column partial sums
__device__ __nv_bfloat16 g_Fh[BB][DD];         // F' = SCALE*(bo + sum_i bp_i*W2_i), bf16
__device__ __nv_bfloat16 g_Wph[MV * DD];       // Wp in bf16
__device__ __nv_bfloat16 g_SW2h[BB][MV * DD];  // SCALE*Cayley-folded Wo, bf16

__device__ __forceinline__ void stcs(float4* p, float4 v) {
    asm volatile("st.global.cs.v4.f32 [%0], {%1,%2,%3,%4};"
                 :: "l"(p), "f"(v.x), "f"(v.y), "f"(v.z), "f"(v.w));
}
// pack {lo, hi} floats -> bf16x2
__device__ __forceinline__ unsigned packbf2(float lo, float hi) {
    unsigned r;
    asm("cvt.rn.bf16x2.f32 %0, %1, %2;" : "=r"(r) : "f"(hi), "f"(lo));
    return r;
}
__device__ __forceinline__ unsigned splatbf2(float x) {
    unsigned r;
    asm("cvt.rn.bf16x2.f32 %0, %1, %2;" : "=r"(r) : "f"(x), "f"(x));
    return r;
}
__device__ __forceinline__ void hfma2acc(unsigned& d, unsigned a, unsigned b) {
    asm("fma.rn.bf16x2 %0, %1, %2, %0;" : "+r"(d) : "r"(a), "r"(b));
}
__device__ __forceinline__ float hsumbf2(unsigned v) {
    float2 f = __bfloat1622float2(*(const __nv_bfloat162*)&v);
    return f.x + f.y;
}

// ---------------------------------------------------------------------------
// Pass 1: pure streaming column sums (proven ~44us @ 79% DRAM).
// ---------------------------------------------------------------------------
__global__ void k_partial(const float* __restrict__ x) {
    int b = blockIdx.y, s = blockIdx.x, t = threadIdx.x;  // t in [0,128)
    const float4* xp = (const float4*)(x + ((size_t)b * NN + (size_t)s * RPS) * DD);
    float4 a0 = make_float4(0.f, 0.f, 0.f, 0.f);
    float4 a1 = make_float4(0.f, 0.f, 0.f, 0.f);
#pragma unroll 4
    for (int r = 0; r < RPS; r += 2) {
        float4 v0 = xp[(size_t)r * 128 + t];
        float4 v1 = xp[(size_t)(r + 1) * 128 + t];
        a0.x += v0.x; a0.y += v0.y; a0.z += v0.z; a0.w += v0.w;
        a1.x += v1.x; a1.y += v1.y; a1.z += v1.z; a1.w += v1.w;
    }
    a0.x += a1.x; a0.y += a1.y; a0.z += a1.z; a0.w += a1.w;
    ((float4*)&g_partial[b][s][0])[t] = a0;
}

// ---------------------------------------------------------------------------
// Pass 2: per-batch prep. mean -> mf -> Cayley fold -> SW2(bf16), F'(bf16),
// Wp(bf16).
// ---------------------------------------------------------------------------
__global__ void k_prep(const float* __restrict__ Wm, const float* __restrict__ bm,
                       const float* __restrict__ Wo, const float* __restrict__ bp,
                       const float* __restrict__ bo, const float* __restrict__ Wp) {
    __shared__ float mean_s[DD];
    __shared__ float mf_s[MV];
    __shared__ float M_s[MV][MV];
    int b = blockIdx.x, t = threadIdx.x;  // 512 threads

    float acc = 0.f;
    for (int s = 0; s < SS; ++s) acc += g_partial[b][s][t];
    mean_s[t] = acc * (1.0f / NN);

#pragma unroll
    for (int i = 0; i < MV; ++i)
        g_Wph[i * DD + t] = __float2bfloat16(Wp[i * DD + t]);
    __syncthreads();

    int w = t >> 5, l = t & 31;
    if (w < MV) {
        float p = 0.f;
#pragma unroll
        for (int c = 0; c < 16; ++c) p += mean_s[l + 32 * c] * Wm[w * DD + l + 32 * c];
#pragma unroll
        for (int o = 16; o; o >>= 1) p += __shfl_xor_sync(0xffffffffu, p, o);
        if (l == 0) mf_s[w] = p + bm[w];
    }
    __syncthreads();

    if (t < 64) {
        const int maskT[8] = {0, 1, 2, 4, 3, 5, 6, 7};
        const int idxT[8]  = {0, 1, 2, 4, 3, 5, 6, 7};
        int i = t >> 3, j = t & 7;
        int a = maskT[i], bj = maskT[j];
        int sgn = 0, aa = a >> 1;
        while (aa) { sgn += __popc(aa & bj); aa >>= 1; }
        int k = idxT[a ^ bj];
        M_s[i][k] = ((sgn & 1) ? -1.f : 1.f) * mf_s[j];
    }
    __syncthreads();

    float wo[8];
#pragma unroll
    for (int k = 0; k < 8; ++k) wo[k] = Wo[t * 8 + k];
    float fb = 0.f;
#pragma unroll
    for (int i = 0; i < MV; ++i) {
        float w2 = 0.f;
#pragma unroll
        for (int k = 0; k < 8; ++k) w2 += M_s[i][k] * wo[k];
        g_SW2h[b][i * DD + t] = __float2bfloat16(SCALE_F * w2);
        fb += bp[i] * w2;
    }
    g_Fh[b][t] = __float2bfloat16(SCALE_F * (fb + bo[t]));
}

// ---------------------------------------------------------------------------
// Pass 3: fused dots + combine + LN. grid (NBLK, BB), 256 threads (8 warps),
// occ 4. Warp: 16 rows, 2/iter. Dots AND outer product in packed HFMA2;
// F folded into accumulator init; 2-FMA normalize.
// ---------------------------------------------------------------------------
__global__ void __launch_bounds__(256, 4)
k_main(const float* __restrict__ x, const float* __restrict__ gamma,
       const float* __restrict__ beta, float* __restrict__ y) {
    __shared__ __nv_bfloat16 Wp_s[MV * DD];    // 8 KB
    __shared__ __nv_bfloat16 SW2_s[MV * DD];   // 8 KB
    __shared__ __nv_bfloat16 F_h[DD];          // 1 KB
    __shared__ float gm_s[DD], bt_s[DD];
    __shared__ float prbuf[2][8][16];          // ping-pong per-warp dot results

    int b = blockIdx.y, t = threadIdx.x;
    const __nv_bfloat16* sw2g = &g_SW2h[b][0];
    for (int i = t; i < MV * DD; i += 256) { Wp_s[i] = g_Wph[i]; SW2_s[i] = sw2g[i]; }
    for (int i = t; i < DD; i += 256) {
        F_h[i] = g_Fh[b][i]; gm_s[i] = gamma[i]; bt_s[i] = beta[i];
    }
    __syncthreads();

    int w = t >> 5, l = t & 31;
    int g = l & 7;
    size_t rowbase = (size_t)blockIdx.x * 128 + (size_t)w * 16;
    const float4* xp = (const float4*)(x + ((size_t)b * NN + rowbase) * DD);
    float4* yp = (float4*)(y + ((size_t)b * NN + rowbase) * DD);

    for (int it = 0; it < 8; ++it) {
        int pp = it & 1;
        float4 v0[4], v1[4];
#pragma unroll
        for (int c = 0; c < 4; ++c) {
            v0[c] = xp[(size_t)(it * 2) * 128 + c * 32 + l];
            v1[c] = xp[(size_t)(it * 2 + 1) * 128 + c * 32 + l];
        }

        // per-row packed dots (HFMA2, Wp pairs straight from smem)
        float p0[8], p1[8];
        {
            unsigned xb[8];
#pragma unroll
            for (int c = 0; c < 4; ++c) {
                xb[2 * c]     = packbf2(v0[c].x, v0[c].y);
                xb[2 * c + 1] = packbf2(v0[c].z, v0[c].w);
            }
#pragma unroll
            for (int i = 0; i < MV; ++i) {
                unsigned acc = 0u;
#pragma unroll
                for (int c = 0; c < 4; ++c) {
                    uint2 u = *(const uint2*)&Wp_s[i * DD + c * 128 + l * 4];
                    hfma2acc(acc, xb[2 * c], u.x);
                    hfma2acc(acc, xb[2 * c + 1], u.y);
                }
                p0[i] = hsumbf2(acc);
            }
#pragma unroll
            for (int c = 0; c < 4; ++c) {
                xb[2 * c]     = packbf2(v1[c].x, v1[c].y);
                xb[2 * c + 1] = packbf2(v1[c].z, v1[c].w);
            }
#pragma unroll
            for (int i = 0; i < MV; ++i) {
                unsigned acc = 0u;
#pragma unroll
                for (int c = 0; c < 4; ++c) {
                    uint2 u = *(const uint2*)&Wp_s[i * DD + c * 128 + l * 4];
                    hfma2acc(acc, xb[2 * c], u.x);
                    hfma2acc(acc, xb[2 * c + 1], u.y);
                }
                p1[i] = hsumbf2(acc);
            }
        }
        // group reduce (1,2,4), select component g, cross-group (8,16)
#pragma unroll
        for (int o = 1; o <= 4; o <<= 1) {
#pragma unroll
            for (int i = 0; i < MV; ++i) {
                p0[i] += __shfl_xor_sync(0xffffffffu, p0[i], o);
                p1[i] += __shfl_xor_sync(0xffffffffu, p1[i], o);
            }
        }
        float vd0 = p0[0], vd1 = p1[0];
#pragma unroll
        for (int i = 1; i < MV; ++i) { if (g == i) { vd0 = p0[i]; vd1 = p1[i]; } }
        vd0 += __shfl_xor_sync(0xffffffffu, vd0, 8);
        vd0 += __shfl_xor_sync(0xffffffffu, vd0, 16);
        vd1 += __shfl_xor_sync(0xffffffffu, vd1, 8);
        vd1 += __shfl_xor_sync(0xffffffffu, vd1, 16);

        // stash dot results in per-warp smem (ping-pong)
        if (l < 16) prbuf[pp][w][l] = (l < 8) ? vd0 : vd1;
        __syncwarp();

        // outer product in packed HFMA2; accumulators init with F' (bf16)
        unsigned acc0[8], acc1[8];
#pragma unroll
        for (int c = 0; c < 4; ++c) {
            uint2 uf = *(const uint2*)&F_h[c * 128 + l * 4];
            acc0[c * 2] = uf.x; acc0[c * 2 + 1] = uf.y;
            acc1[c * 2] = uf.x; acc1[c * 2 + 1] = uf.y;
        }
#pragma unroll
        for (int i = 0; i < MV; ++i) {
            unsigned a2 = splatbf2(prbuf[pp][w][i]);
            unsigned b2 = splatbf2(prbuf[pp][w][8 + i]);
#pragma unroll
            for (int c = 0; c < 4; ++c) {
                uint2 u = *(const uint2*)&SW2_s[i * DD + c * 128 + l * 4];
                hfma2acc(acc0[c * 2],     a2, u.x);
                hfma2acc(acc0[c * 2 + 1], a2, u.y);
                hfma2acc(acc1[c * 2],     b2, u.x);
                hfma2acc(acc1[c * 2 + 1], b2, u.y);
            }
        }
        // v = x + (F' + outer)
#pragma unroll
        for (int c = 0; c < 4; ++c) {
            float2 e0 = __bfloat1622float2(*(const __nv_bfloat162*)&acc0[c * 2]);
            float2 e1 = __bfloat1622float2(*(const __nv_bfloat162*)&acc0[c * 2 + 1]);
            float2 e2 = __bfloat1622float2(*(const __nv_bfloat162*)&acc1[c * 2]);
            float2 e3 = __bfloat1622float2(*(const __nv_bfloat162*)&acc1[c * 2 + 1]);
            v0[c].x += e0.x; v0[c].y += e0.y;
            v0[c].z += e1.x; v0[c].w += e1.y;
            v1[c].x += e2.x; v1[c].y += e2.y;
            v1[c].z += e3.x; v1[c].w += e3.y;
        }

        // LayerNorm stats: group reduce + 4-way select + cross
        float s0 = 0.f, q0 = 0.f, s1 = 0.f, q1 = 0.f;
#pragma unroll
        for (int c = 0; c < 4; ++c) {
            s0 += v0[c].x + v0[c].y + v0[c].z + v0[c].w;
            q0 += v0[c].x * v0[c].x + v0[c].y * v0[c].y + v0[c].z * v0[c].z + v0[c].w * v0[c].w;
            s1 += v1[c].x + v1[c].y + v1[c].z + v1[c].w;
            q1 += v1[c].x * v1[c].x + v1[c].y * v1[c].y + v1[c].z * v1[c].z + v1[c].w * v1[c].w;
        }
#pragma unroll
        for (int o = 1; o <= 2; o <<= 1) {
            s0 += __shfl_xor_sync(0xffffffffu, s0, o);
            q0 += __shfl_xor_sync(0xffffffffu, q0, o);
            s1 += __shfl_xor_sync(0xffffffffu, s1, o);
            q1 += __shfl_xor_sync(0xffffffffu, q1, o);
        }
        int g4i = l & 3;
        float sel = s0;
        if (g4i == 1) sel = q0;
        if (g4i == 2) sel = s1;
        if (g4i == 3) sel = q1;
        sel += __shfl_xor_sync(0xffffffffu, sel, 4);
        sel += __shfl_xor_sync(0xffffffffu, sel, 8);
        sel += __shfl_xor_sync(0xffffffffu, sel, 16);
        float S0 = __shfl_sync(0xffffffffu, sel, 0);
        float Q0 = __shfl_sync(0xffffffffu, sel, 1);
        float S1 = __shfl_sync(0xffffffffu, sel, 2);
        float Q1 = __shfl_sync(0xffffffffu, sel, 3);

        float mu0 = S0 * (1.f / DD), mu1 = S1 * (1.f / DD);
        float r0 = rsqrtf(Q0 * (1.f / DD) - mu0 * mu0 + EPS_F);
        float r1 = rsqrtf(Q1 * (1.f / DD) - mu1 * mu1 + EPS_F);
        float mr0 = -mu0 * r0, mr1 = -mu1 * r1;

        // 2-FMA normalize: e = fma(v, r, mr); o = fma(g, e, b)
#pragma unroll
        for (int c = 0; c < 4; ++c) {
            float4 g4 = *(const float4*)&gm_s[c * 128 + l * 4];
            float4 b4 = *(const float4*)&bt_s[c * 128 + l * 4];
            float4 o0, o1;
            o0.x = fmaf(g4.x, fmaf(v0[c].x, r0, mr0), b4.x);
            o0.y = fmaf(g4.y, fmaf(v0[c].y, r0, mr0), b4.y);
            o0.z = fmaf(g4.z, fmaf(v0[c].z, r0, mr0), b4.z);
            o0.w = fmaf(g4.w, fmaf(v0[c].w, r0, mr0), b4.w);
            o1.x = fmaf(g4.x, fmaf(v1[c].x, r1, mr1), b4.x);
            o1.y = fmaf(g4.y, fmaf(v1[c].y, r1, mr1), b4.y);
            o1.z = fmaf(g4.z, fmaf(v1[c].z, r1, mr1), b4.z);
            o1.w = fmaf(g4.w, fmaf(v1[c].w, r1, mr1), b4.w);
            stcs(&yp[(size_t)(it * 2) * 128 + c * 32 + l], o0);
            stcs(&yp[(size_t)(it * 2 + 1) * 128 + c * 32 + l], o1);
        }
    }
}

// ---------------------------------------------------------------------------
extern "C" void kernel_launch(void* const* d_in, const int* in_sizes, int n_in,
                              void* d_out, int out_size) {
    const float* x     = (const float*)d_in[0];
    const float* Wp    = (const float*)d_in[1];
    const float* bp    = (const float*)d_in[2];
    const float* Wm    = (const float*)d_in[3];
    const float* bm    = (const float*)d_in[4];
    const float* Wo    = (const float*)d_in[5];
    const float* bo    = (const float*)d_in[6];
    const float* gamma = (const float*)d_in[7];
    const float* beta  = (const float*)d_in[8];
    float* y = (float*)d_out;

    dim3 g1(SS, BB);
    k_partial<<<g1, 128>>>(x);
    k_prep<<<BB, 512>>>(Wm, bm, Wo, bp, bo, Wp);
    dim3 g3(NBLK, BB);
    k_main<<<g3, 256>>>(x, gamma, beta, y);
}

// round 14
// speedup vs baseline: 1.0185x; 1.0185x over previous
#include <cuda_runtime.h>
#include <cuda_bf16.h>

#define BB 8
#define NN 16384
#define DD 512
#define MV 8
#define SS 128                      // N-splits in pass 1
#define RPS (NN / SS)               // rows per split = 128
#define NBLK 128                    // blocks per batch in pass 3
#define SCALE_F 0.1f
#define EPS_F 1e-5f

__device__ float g_partial[BB][SS][DD];        // 2 MB  column partial sums
__device__ __nv_bfloat16 g_Fh[BB][DD];         // F' = SCALE*(bo + sum bp_i*W2_i), bf16
__device__ __nv_bfloat16 g_Wph[MV * DD];       // Wp in bf16
__device__ __nv_bfloat16 g_SW2h[BB][MV * DD];  // SCALE*Cayley-folded Wo, bf16

__device__ __forceinline__ void stcs(float4* p, float4 v) {
    asm volatile("st.global.cs.v4.f32 [%0], {%1,%2,%3,%4};"
                 :: "l"(p), "f"(v.x), "f"(v.y), "f"(v.z), "f"(v.w));
}
__device__ __forceinline__ unsigned splatbf2(float x) {
    unsigned r;
    asm("cvt.rn.bf16x2.f32 %0, %1, %2;" : "=r"(r) : "f"(x), "f"(x));
    return r;
}
__device__ __forceinline__ void hfma2acc(unsigned& d, unsigned a, unsigned b) {
    asm("fma.rn.bf16x2 %0, %1, %2, %0;" : "+r"(d) : "r"(a), "r"(b));
}

// ---------------------------------------------------------------------------
// Pass 1: pure streaming column sums (proven ~44us @ 79% DRAM).
// ---------------------------------------------------------------------------
__global__ void k_partial(const float* __restrict__ x) {
    int b = blockIdx.y, s = blockIdx.x, t = threadIdx.x;  // t in [0,128)
    const float4* xp = (const float4*)(x + ((size_t)b * NN + (size_t)s * RPS) * DD);
    float4 a0 = make_float4(0.f, 0.f, 0.f, 0.f);
    float4 a1 = make_float4(0.f, 0.f, 0.f, 0.f);
#pragma unroll 4
    for (int r = 0; r < RPS; r += 2) {
        float4 v0 = xp[(size_t)r * 128 + t];
        float4 v1 = xp[(size_t)(r + 1) * 128 + t];
        a0.x += v0.x; a0.y += v0.y; a0.z += v0.z; a0.w += v0.w;
        a1.x += v1.x; a1.y += v1.y; a1.z += v1.z; a1.w += v1.w;
    }
    a0.x += a1.x; a0.y += a1.y; a0.z += a1.z; a0.w += a1.w;
    ((float4*)&g_partial[b][s][0])[t] = a0;
}

// ---------------------------------------------------------------------------
// Pass 2: per-batch prep. mean -> mf -> Cayley fold -> SW2(bf16), F'(bf16),
// Wp(bf16).
// ---------------------------------------------------------------------------
__global__ void k_prep(const float* __restrict__ Wm, const float* __restrict__ bm,
                       const float* __restrict__ Wo, const float* __restrict__ bp,
                       const float* __restrict__ bo, const float* __restrict__ Wp) {
    __shared__ float mean_s[DD];
    __shared__ float mf_s[MV];
    __shared__ float M_s[MV][MV];
    int b = blockIdx.x, t = threadIdx.x;  // 512 threads

    float acc = 0.f;
    for (int s = 0; s < SS; ++s) acc += g_partial[b][s][t];
    mean_s[t] = acc * (1.0f / NN);

#pragma unroll
    for (int i = 0; i < MV; ++i)
        g_Wph[i * DD + t] = __float2bfloat16(Wp[i * DD + t]);
    __syncthreads();

    int w = t >> 5, l = t & 31;
    if (w < MV) {
        float p = 0.f;
#pragma unroll
        for (int c = 0; c < 16; ++c) p += mean_s[l + 32 * c] * Wm[w * DD + l + 32 * c];
#pragma unroll
        for (int o = 16; o; o >>= 1) p += __shfl_xor_sync(0xffffffffu, p, o);
        if (l == 0) mf_s[w] = p + bm[w];
    }
    __syncthreads();

    if (t < 64) {
        const int maskT[8] = {0, 1, 2, 4, 3, 5, 6, 7};
        const int idxT[8]  = {0, 1, 2, 4, 3, 5, 6, 7};
        int i = t >> 3, j = t & 7;
        int a = maskT[i], bj = maskT[j];
        int sgn = 0, aa = a >> 1;
        while (aa) { sgn += __popc(aa & bj); aa >>= 1; }
        int k = idxT[a ^ bj];
        M_s[i][k] = ((sgn & 1) ? -1.f : 1.f) * mf_s[j];
    }
    __syncthreads();

    float wo[8];
#pragma unroll
    for (int k = 0; k < 8; ++k) wo[k] = Wo[t * 8 + k];
    float fb = 0.f;
#pragma unroll
    for (int i = 0; i < MV; ++i) {
        float w2 = 0.f;
#pragma unroll
        for (int k = 0; k < 8; ++k) w2 += M_s[i][k] * wo[k];
        g_SW2h[b][i * DD + t] = __float2bfloat16(SCALE_F * w2);
        fb += bp[i] * w2;
    }
    g_Fh[b][t] = __float2bfloat16(SCALE_F * (fb + bo[t]));
}

// ---------------------------------------------------------------------------
// Pass 3: fused dots + combine + LN. grid (NBLK, BB), 256 threads (8 warps),
// occ 4. Warp: 16 rows, 2/iter. fp32 dots; HFMA2 outer w/ F-fold;
// LDS.128 weight reads; 2-FMA normalize.
// ---------------------------------------------------------------------------
__global__ void __launch_bounds__(256, 4)
k_main(const float* __restrict__ x, const float* __restrict__ gamma,
       const float* __restrict__ beta, float* __restrict__ y) {
    __shared__ __nv_bfloat16 Wp_s[MV * DD];    // 8 KB
    __shared__ __nv_bfloat16 SW2_s[MV * DD];   // 8 KB
    __shared__ __nv_bfloat16 F_h[DD];          // 1 KB
    __shared__ float gm_s[DD], bt_s[DD];
    __shared__ float prbuf[2][8][16];          // ping-pong per-warp dot results

    int b = blockIdx.y, t = threadIdx.x;
    const __nv_bfloat16* sw2g = &g_SW2h[b][0];
    for (int i = t; i < MV * DD; i += 256) { Wp_s[i] = g_Wph[i]; SW2_s[i] = sw2g[i]; }
    for (int i = t; i < DD; i += 256) {
        F_h[i] = g_Fh[b][i]; gm_s[i] = gamma[i]; bt_s[i] = beta[i];
    }
    __syncthreads();

    int w = t >> 5, l = t & 31;
    int g = l & 7;
    size_t rowbase = (size_t)blockIdx.x * 128 + (size_t)w * 16;
    const float4* xp = (const float4*)(x + ((size_t)b * NN + rowbase) * DD);
    float4* yp = (float4*)(y + ((size_t)b * NN + rowbase) * DD);

    // lane's 16-bf16 slice base within a weight row: pairs at c*128 + l*4,
    // laid out so one uint4 covers c=0,1 and another covers c=2,3 when
    // addressed as [i*DD + l*4 + c*128]. We fetch per-c uint2 via uint4:
    // uint4 at (i*DD + l*8) is NOT layout-compatible; instead read two uint4
    // per i covering (c=0,c=1) and (c=2,c=3): offsets l*4 and 256 + l*4 are
    // 128 apart per c, so a uint4 spans 8 consecutive bf16 = c and c+... no.
    // Layout truth: element d = c*128 + l*4 + j. Consecutive c blocks are 128
    // elements (256 B) apart -> NOT contiguous. So keep per-c loads but use
    // one LDS.128 to grab BOTH weight rows' worth? Also not contiguous.
    // => use uint2 per (i,c) as before for correctness.

    for (int it = 0; it < 8; ++it) {
        int pp = it & 1;
        float4 v0[4], v1[4];
#pragma unroll
        for (int c = 0; c < 4; ++c) {
            v0[c] = xp[(size_t)(it * 2) * 128 + c * 32 + l];
            v1[c] = xp[(size_t)(it * 2 + 1) * 128 + c * 32 + l];
        }

        // 8 per-lane partial dots per row (fp32 FFMA, bf16 weights)
        float p0[8], p1[8];
#pragma unroll
        for (int i = 0; i < MV; ++i) {
            float s0 = 0.f, s1 = 0.f;
#pragma unroll
            for (int c = 0; c < 4; ++c) {
                uint2 u = *(const uint2*)&Wp_s[i * DD + c * 128 + l * 4];
                float2 a01 = __bfloat1622float2(*(const __nv_bfloat162*)&u.x);
                float2 a23 = __bfloat1622float2(*(const __nv_bfloat162*)&u.y);
                s0 += v0[c].x * a01.x + v0[c].y * a01.y + v0[c].z * a23.x + v0[c].w * a23.y;
                s1 += v1[c].x * a01.x + v1[c].y * a01.y + v1[c].z * a23.x + v1[c].w * a23.y;
            }
            p0[i] = s0; p1[i] = s1;
        }
        // group reduce (1,2,4), select component g, cross-group (8,16)
#pragma unroll
        for (int o = 1; o <= 4; o <<= 1) {
#pragma unroll
            for (int i = 0; i < MV; ++i) {
                p0[i] += __shfl_xor_sync(0xffffffffu, p0[i], o);
                p1[i] += __shfl_xor_sync(0xffffffffu, p1[i], o);
            }
        }
        float vd0 = p0[0], vd1 = p1[0];
#pragma unroll
        for (int i = 1; i < MV; ++i) { if (g == i) { vd0 = p0[i]; vd1 = p1[i]; } }
        vd0 += __shfl_xor_sync(0xffffffffu, vd0, 8);
        vd0 += __shfl_xor_sync(0xffffffffu, vd0, 16);
        vd1 += __shfl_xor_sync(0xffffffffu, vd1, 8);
        vd1 += __shfl_xor_sync(0xffffffffu, vd1, 16);

        // stash dot results in per-warp smem (ping-pong)
        if (l < 16) prbuf[pp][w][l] = (l < 8) ? vd0 : vd1;
        __syncwarp();

        // outer product in packed HFMA2; accumulators init with F' (bf16)
        unsigned acc0[8], acc1[8];
#pragma unroll
        for (int c = 0; c < 4; ++c) {
            uint2 uf = *(const uint2*)&F_h[c * 128 + l * 4];
            acc0[c * 2] = uf.x; acc0[c * 2 + 1] = uf.y;
            acc1[c * 2] = uf.x; acc1[c * 2 + 1] = uf.y;
        }
#pragma unroll
        for (int i = 0; i < MV; ++i) {
            unsigned a2 = splatbf2(prbuf[pp][w][i]);
            unsigned b2 = splatbf2(prbuf[pp][w][8 + i]);
#pragma unroll
            for (int c = 0; c < 4; ++c) {
                uint2 u = *(const uint2*)&SW2_s[i * DD + c * 128 + l * 4];
                hfma2acc(acc0[c * 2],     a2, u.x);
                hfma2acc(acc0[c * 2 + 1], a2, u.y);
                hfma2acc(acc1[c * 2],     b2, u.x);
                hfma2acc(acc1[c * 2 + 1], b2, u.y);
            }
        }
        // v = x + (F' + outer)
#pragma unroll
        for (int c = 0; c < 4; ++c) {
            float2 e0 = __bfloat1622float2(*(const __nv_bfloat162*)&acc0[c * 2]);
            float2 e1 = __bfloat1622float2(*(const __nv_bfloat162*)&acc0[c * 2 + 1]);
            float2 e2 = __bfloat1622float2(*(const __nv_bfloat162*)&acc1[c * 2]);
            float2 e3 = __bfloat1622float2(*(const __nv_bfloat162*)&acc1[c * 2 + 1]);
            v0[c].x += e0.x; v0[c].y += e0.y;
            v0[c].z += e1.x; v0[c].w += e1.y;
            v1[c].x += e2.x; v1[c].y += e2.y;
            v1[c].z += e3.x; v1[c].w += e3.y;
        }

        // LayerNorm stats: group reduce + 4-way select + cross
        float s0 = 0.f, q0 = 0.f, s1 = 0.f, q1 = 0.f;
#pragma unroll
        for (int c = 0; c < 4; ++c) {
            s0 += v0[c].x + v0[c].y + v0[c].z + v0[c].w;
            q0 += v0[c].x * v0[c].x + v0[c].y * v0[c].y + v0[c].z * v0[c].z + v0[c].w * v0[c].w;
            s1 += v1[c].x + v1[c].y + v1[c].z + v1[c].w;
            q1 += v1[c].x * v1[c].x + v1[c].y * v1[c].y + v1[c].z * v1[c].z + v1[c].w * v1[c].w;
        }
#pragma unroll
        for (int o = 1; o <= 2; o <<= 1) {
            s0 += __shfl_xor_sync(0xffffffffu, s0, o);
            q0 += __shfl_xor_sync(0xffffffffu, q0, o);
            s1 += __shfl_xor_sync(0xffffffffu, s1, o);
            q1 += __shfl_xor_sync(0xffffffffu, q1, o);
        }
        int g4i = l & 3;
        float sel = s0;
        if (g4i == 1) sel = q0;
        if (g4i == 2) sel = s1;
        if (g4i == 3) sel = q1;
        sel += __shfl_xor_sync(0xffffffffu, sel, 4);
        sel += __shfl_xor_sync(0xffffffffu, sel, 8);
        sel += __shfl_xor_sync(0xffffffffu, sel, 16);
        float S0 = __shfl_sync(0xffffffffu, sel, 0);
        float Q0 = __shfl_sync(0xffffffffu, sel, 1);
        float S1 = __shfl_sync(0xffffffffu, sel, 2);
        float Q1 = __shfl_sync(0xffffffffu, sel, 3);

        float mu0 = S0 * (1.f / DD), mu1 = S1 * (1.f / DD);
        float r0 = rsqrtf(Q0 * (1.f / DD) - mu0 * mu0 + EPS_F);
        float r1 = rsqrtf(Q1 * (1.f / DD) - mu1 * mu1 + EPS_F);
        float mr0 = -mu0 * r0, mr1 = -mu1 * r1;

        // 2-FMA normalize: e = fma(v, r, mr); o = fma(g, e, b)
#pragma unroll
        for (int c = 0; c < 4; ++c) {
            float4 g4 = *(const float4*)&gm_s[c * 128 + l * 4];
            float4 b4 = *(const float4*)&bt_s[c * 128 + l * 4];
            float4 o0, o1;
            o0.x = fmaf(g4.x, fmaf(v0[c].x, r0, mr0), b4.x);
            o0.y = fmaf(g4.y, fmaf(v0[c].y, r0, mr0), b4.y);
            o0.z = fmaf(g4.z, fmaf(v0[c].z, r0, mr0), b4.z);
            o0.w = fmaf(g4.w, fmaf(v0[c].w, r0, mr0), b4.w);
            o1.x = fmaf(g4.x, fmaf(v1[c].x, r1, mr1), b4.x);
            o1.y = fmaf(g4.y, fmaf(v1[c].y, r1, mr1), b4.y);
            o1.z = fmaf(g4.z, fmaf(v1[c].z, r1, mr1), b4.z);
            o1.w = fmaf(g4.w, fmaf(v1[c].w, r1, mr1), b4.w);
            stcs(&yp[(size_t)(it * 2) * 128 + c * 32 + l], o0);
            stcs(&yp[(size_t)(it * 2 + 1) * 128 + c * 32 + l], o1);
        }
    }
}

// ---------------------------------------------------------------------------
extern "C" void kernel_launch(void* const* d_in, const int* in_sizes, int n_in,
                              void* d_out, int out_size) {
    const float* x     = (const float*)d_in[0];
    const float* Wp    = (const float*)d_in[1];
    const float* bp    = (const float*)d_in[2];
    const float* Wm    = (const float*)d_in[3];
    const float* bm    = (const float*)d_in[4];
    const float* Wo    = (const float*)d_in[5];
    const float* bo    = (const float*)d_in[6];
    const float* gamma = (const float*)d_in[7];
    const float* beta  = (const float*)d_in[8];
    float* y = (float*)d_out;

    dim3 g1(SS, BB);
    k_partial<<<g1, 128>>>(x);
    k_prep<<<BB, 512>>>(Wm, bm, Wo, bp, bo, Wp);
    dim3 g3(NBLK, BB);
    k_main<<<g3, 256>>>(x, gamma, beta, y);
}